// round 16
// baseline (speedup 1.0000x reference)
#include <cuda_runtime.h>
#include <cuda_bf16.h>
#include <cstdint>

#define BB 16
#define CC 256
#define NN 4096
#define DA 64
#define TI 64
#define TJ 128

typedef unsigned long long u64;

#define MMA_BF16(d0,d1,d2,d3,a0,a1,a2,a3,b0,b1) \
    asm volatile("mma.sync.aligned.m16n8k16.row.col.f32.bf16.bf16.f32 " \
        "{%0,%1,%2,%3}, {%4,%5,%6,%7}, {%8,%9}, {%0,%1,%2,%3};" \
        : "+f"(d0), "+f"(d1), "+f"(d2), "+f"(d3) \
        : "r"(a0), "r"(a1), "r"(a2), "r"(a3), "r"(b0), "r"(b1))

#define PACK_BF16X2(d, lo, hi) \
    asm("cvt.rn.bf16x2.f32 %0, %1, %2;" : "=r"(d) : "f"(hi), "f"(lo))

#define LDSM_X4(r0,r1,r2,r3, addr) \
    asm volatile("ldmatrix.sync.aligned.m8n8.x4.shared.b16 {%0,%1,%2,%3}, [%4];" \
        : "=r"(r0), "=r"(r1), "=r"(r2), "=r"(r3) : "r"(addr))

#define LDSM_T_X4(r0,r1,r2,r3, addr) \
    asm volatile("ldmatrix.sync.aligned.m8n8.x4.trans.shared.b16 {%0,%1,%2,%3}, [%4];" \
        : "=r"(r0), "=r"(r1), "=r"(r2), "=r"(r3) : "r"(addr))

// cp.async (sm_80+)
#define CP_ASYNC16(dst, src) \
    asm volatile("cp.async.cg.shared.global [%0], [%1], 16;" :: "r"(dst), "l"(src) : "memory")
#define CP_COMMIT() asm volatile("cp.async.commit_group;" ::: "memory")
#define CP_WAIT(n)  asm volatile("cp.async.wait_group %0;" :: "n"(n) : "memory")

// Scratch (bf16)
__device__ __nv_bfloat16 g_q[(size_t)BB * NN * DA];   // [b][n][a] (pre-scaled log2e/64)
__device__ __nv_bfloat16 g_k[(size_t)BB * NN * DA];   // [b][n][a]
__device__ __nv_bfloat16 g_v[(size_t)BB * CC * NN];   // [b][c][n] TRANSPOSED

__device__ __forceinline__ uint32_t smem_u32(const void* p) {
    uint32_t a;
    asm("{ .reg .u64 t; cvta.to.shared.u64 t, %1; cvt.u32.u64 %0, t; }" : "=r"(a) : "l"(p));
    return a;
}

// ---------------------------------------------------------------------------
// Kernel 1: fused QKV projection via bf16 mma.sync (UNCHANGED from round 10).
// ---------------------------------------------------------------------------
#define PW_STR 132
#define PX_STR 68
#define POW  0
#define POX0 (128 * PW_STR)
#define POX1 (POX0 + 64 * PX_STR)
#define PSMW (POX1 + 64 * PX_STR)

__global__ __launch_bounds__(256, 1) void proj_kernel(
    const float* __restrict__ x,
    const float* __restrict__ Wq, const float* __restrict__ bq,
    const float* __restrict__ Wk, const float* __restrict__ bk,
    const float* __restrict__ Wv, const float* __restrict__ bv)
{
    extern __shared__ __align__(16) uint32_t psm[];
    const uint32_t smb = smem_u32(psm);

    const int t    = threadIdx.x;
    const int lane = t & 31;
    const int wid  = t >> 5;
    const int g    = lane >> 2;
    const int tg   = lane & 3;
    const int lrow = lane & 7;
    const int q8   = lane >> 3;
    const int rg   = blockIdx.y;
    const int b    = blockIdx.z;
    const int nbase = blockIdx.x * 512;

    for (int f = t; f < 128 * 128; f += 256) {
        int r = f >> 7, cw = f & 127;
        const float* wrow;
        if (rg == 0) wrow = (r < 64) ? (Wq + r * CC) : (Wk + (r - 64) * CC);
        else         wrow = Wv + ((size_t)((rg - 1) * 128 + r)) * CC;
        float2 wv = *(const float2*)&wrow[cw * 2];
        uint32_t pk; PACK_BF16X2(pk, wv.x, wv.y);
        psm[r * PW_STR + cw] = pk;
    }
    __syncthreads();

    uint32_t af[16][4];
    {
        const uint32_t abase = smb + 4 * ((wid * 16 + (q8 & 1) * 8 + lrow) * PW_STR + (q8 >> 1) * 4);
#pragma unroll
        for (int s = 0; s < 16; s++)
            LDSM_X4(af[s][0], af[s][1], af[s][2], af[s][3], abase + 4 * (s * 8));
    }

    const int row_g = wid * 16 + g;
    float bias_lo, bias_hi;
    if (rg == 0) {
        if (wid < 4) { bias_lo = bq[row_g]; bias_hi = bq[row_g + 8]; }
        else         { bias_lo = bk[row_g - 64]; bias_hi = bk[row_g - 56]; }
    } else {
        bias_lo = bv[(rg - 1) * 128 + row_g];
        bias_hi = bv[(rg - 1) * 128 + row_g + 8];
    }
    const float qscale = 1.4426950408889634f / 64.0f;

    const uint32_t xrowpart = ((q8 & 1) * 8 + lrow) * PX_STR * 4 + (q8 >> 1) * 16;

    float4 pf[8];
#pragma unroll
    for (int i = 0; i < 8; i++)
        pf[i] = *(const float4*)&x[((size_t)b * CC + i * 8 + (t >> 5)) * NN + nbase + (t & 31) * 4];

    for (int tile = 0; tile < 4; tile++) {
        const int n0 = nbase + tile * 128;

        float acc[16][4];
#pragma unroll
        for (int nb = 0; nb < 16; nb++)
#pragma unroll
            for (int r = 0; r < 4; r++) acc[nb][r] = 0.f;

        for (int ck = 0; ck < 4; ck++) {
            __syncthreads();
            uint32_t* xb = psm + ((ck & 1) ? POX1 : POX0);
#pragma unroll
            for (int i = 0; i < 8; i++) {
                int c = i * 8 + (t >> 5);
                uint32_t w0, w1;
                PACK_BF16X2(w0, pf[i].x, pf[i].y);
                PACK_BF16X2(w1, pf[i].z, pf[i].w);
                *(uint2*)&xb[c * PX_STR + (t & 31) * 2] = make_uint2(w0, w1);
            }
            __syncthreads();

            if (ck < 3) {
                int cb = (ck + 1) * 64;
#pragma unroll
                for (int i = 0; i < 8; i++)
                    pf[i] = *(const float4*)&x[((size_t)b * CC + cb + i * 8 + (t >> 5)) * NN + n0 + (t & 31) * 4];
            } else if (tile < 3) {
                int n0n = nbase + (tile + 1) * 128;
#pragma unroll
                for (int i = 0; i < 8; i++)
                    pf[i] = *(const float4*)&x[((size_t)b * CC + i * 8 + (t >> 5)) * NN + n0n + (t & 31) * 4];
            }

            const uint32_t xtbase = smb + 4 * ((ck & 1) ? POX1 : POX0) + xrowpart;
#pragma unroll
            for (int s = 0; s < 4; s++) {
                const int astep = ck * 4 + s;
#pragma unroll
                for (int nbp = 0; nbp < 8; nbp++) {
                    uint32_t b0, b1, b2, b3;
                    LDSM_T_X4(b0, b1, b2, b3, xtbase + s * 16 * PX_STR * 4 + nbp * 32);
                    MMA_BF16(acc[nbp*2][0], acc[nbp*2][1], acc[nbp*2][2], acc[nbp*2][3],
                             af[astep][0], af[astep][1], af[astep][2], af[astep][3], b0, b1);
                    MMA_BF16(acc[nbp*2+1][0], acc[nbp*2+1][1], acc[nbp*2+1][2], acc[nbp*2+1][3],
                             af[astep][0], af[astep][1], af[astep][2], af[astep][3], b2, b3);
                }
            }
        }

        if (rg != 0) {
            const int clo = (rg - 1) * 128 + wid * 16 + g;
#pragma unroll
            for (int nb = 0; nb < 16; nb++) {
                uint32_t w0, w1;
                PACK_BF16X2(w0, acc[nb][0] + bias_lo, acc[nb][1] + bias_lo);
                PACK_BF16X2(w1, acc[nb][2] + bias_hi, acc[nb][3] + bias_hi);
                *(uint32_t*)&g_v[((size_t)b * CC + clo) * NN + n0 + nb * 8 + 2 * tg] = w0;
                *(uint32_t*)&g_v[((size_t)b * CC + clo + 8) * NN + n0 + nb * 8 + 2 * tg] = w1;
            }
        } else {
            __syncthreads();
            uint32_t* dstbuf = psm + ((wid < 4) ? POX0 : POX1);
            const int rloc = (wid & 3) * 16 + g;
            const bool isq = (wid < 4);
            const float sc = isq ? qscale : 1.0f;
#pragma unroll
            for (int nb = 0; nb < 16; nb++) {
                uint32_t w0, w1;
                PACK_BF16X2(w0, (acc[nb][0] + bias_lo) * sc, (acc[nb][1] + bias_lo) * sc);
                PACK_BF16X2(w1, (acc[nb][2] + bias_hi) * sc, (acc[nb][3] + bias_hi) * sc);
                dstbuf[(rloc    ) * PX_STR + nb * 4 + tg] = w0;
                dstbuf[(rloc + 8) * PX_STR + nb * 4 + tg] = w1;
            }
            __syncthreads();
            const int nn = t & 127, half = t >> 7;
            const uint16_t* s16q = (const uint16_t*)(psm + POX0);
            const uint16_t* s16k = (const uint16_t*)(psm + POX1);
            uint32_t wout[16];
#pragma unroll
            for (int i = 0; i < 16; i++) {
                uint32_t lo = s16q[(half * 32 + 2 * i    ) * (PX_STR * 2) + nn];
                uint32_t hi = s16q[(half * 32 + 2 * i + 1) * (PX_STR * 2) + nn];
                wout[i] = lo | (hi << 16);
            }
            {
                uint4* p = (uint4*)&g_q[((size_t)b * NN + n0 + nn) * DA + half * 32];
                p[0] = make_uint4(wout[0], wout[1], wout[2], wout[3]);
                p[1] = make_uint4(wout[4], wout[5], wout[6], wout[7]);
                p[2] = make_uint4(wout[8], wout[9], wout[10], wout[11]);
                p[3] = make_uint4(wout[12], wout[13], wout[14], wout[15]);
            }
#pragma unroll
            for (int i = 0; i < 16; i++) {
                uint32_t lo = s16k[(half * 32 + 2 * i    ) * (PX_STR * 2) + nn];
                uint32_t hi = s16k[(half * 32 + 2 * i + 1) * (PX_STR * 2) + nn];
                wout[i] = lo | (hi << 16);
            }
            {
                uint4* p = (uint4*)&g_k[((size_t)b * NN + n0 + nn) * DA + half * 32];
                p[0] = make_uint4(wout[0], wout[1], wout[2], wout[3]);
                p[1] = make_uint4(wout[4], wout[5], wout[6], wout[7]);
                p[2] = make_uint4(wout[8], wout[9], wout[10], wout[11]);
                p[3] = make_uint4(wout[12], wout[13], wout[14], wout[15]);
            }
        }
    }
}

// ---------------------------------------------------------------------------
// Kernel 2: bf16 mma.sync flash attention. TI=64, TJ=128, 8 warps =
// 4 i-blocks (16 rows) x {jh for S | ch for PV}. Non-redundant S (each warp
// 16 rows x 64 j), P exchanged via smem. O = 64 regs/thread -> ~90 regs of
// scheduling headroom for LDSM hoisting (the R12/R15 confounds removed).
// ---------------------------------------------------------------------------
#define KSTRW 36                    // K row stride (words)
#define VSTRW 68                    // V row stride (words)
#define PSTRW 68                    // P row stride (words)
#define KW  (TJ * KSTRW)            // 4608
#define VW  (CC * VSTRW)            // 17408
#define OKS0 0
#define OVS0 KW
#define OKS1 (KW + VW)
#define OVS1 (2 * KW + VW)
#define OPS  (2 * (KW + VW))        // 44032
#define OLS  (OPS + TI * PSTRW)     // 48384
#define SMW  (OLS + 2 * 64)         // 48512 words = 194048 B

__global__ __launch_bounds__(256, 1) void attn_kernel(
    const float* __restrict__ x, float* __restrict__ out)
{
    extern __shared__ __align__(16) uint32_t sm[];
    const uint32_t smb = smem_u32(sm);

    const int t    = threadIdx.x;
    const int lane = t & 31;
    const int wid  = t >> 5;
    const int ig   = wid >> 1;      // i-block: rows ig*16 .. +15
    const int jh   = wid & 1;       // S: j-half (64 of 128)
    const int ch   = wid & 1;       // PV: c-half (128 of 256)
    const int g    = lane >> 2;
    const int tg   = lane & 3;
    const int b    = blockIdx.y;
    const int i0   = blockIdx.x * TI;

    const int lrow = lane & 7;
    const int q8   = lane >> 3;
    const int bqr  = q8 >> 1, bqc = q8 & 1;   // B-frag quads
    const int aqr  = q8 & 1,  aqc = q8 >> 1;  // A-frag quads
    const uint32_t krowpart = 4 * ((bqr * 8 + lrow) * KSTRW + bqc * 4);
    const uint32_t vrowpart = 4 * ((ch * 128 + bqr * 8 + lrow) * VSTRW + bqc * 4);
    const uint32_t pldbase  = smb + 4 * (OPS + (ig * 16 + aqr * 8 + lrow) * PSTRW + aqc * 4);

    // ---- Q fragments: 16 rows x 4 k16-steps ----
    uint32_t qa[4][4];
    {
        const __nv_bfloat16* qg = g_q + ((size_t)b * NN + i0 + ig * 16) * DA;
#pragma unroll
        for (int s = 0; s < 4; s++) {
            qa[s][0] = *(const uint32_t*)&qg[(size_t)(g    ) * DA + s * 16 + 2 * tg    ];
            qa[s][1] = *(const uint32_t*)&qg[(size_t)(g + 8) * DA + s * 16 + 2 * tg    ];
            qa[s][2] = *(const uint32_t*)&qg[(size_t)(g    ) * DA + s * 16 + 2 * tg + 8];
            qa[s][3] = *(const uint32_t*)&qg[(size_t)(g + 8) * DA + s * 16 + 2 * tg + 8];
        }
    }

    float o[16][4];
#pragma unroll
    for (int n = 0; n < 16; n++)
#pragma unroll
        for (int r = 0; r < 4; r++) o[n][r] = 0.f;

    float l0 = 0.f, l1 = 0.f;

    const __nv_bfloat16* kgb = g_k + (size_t)b * NN * DA;
    const __nv_bfloat16* vgb = g_v + (size_t)b * CC * NN;

    // ---- prologue: stage tile 0 into buffer 0 ----
    {
        uint32_t kdst = smb + OKS0 * 4;
#pragma unroll
        for (int f = t; f < 1024; f += 256) {
            int r = f >> 3, c4 = f & 7;
            CP_ASYNC16(kdst + (r * KSTRW + c4 * 4) * 4, kgb + (size_t)r * DA + c4 * 8);
        }
        uint32_t vdst = smb + OVS0 * 4;
#pragma unroll
        for (int f = t; f < 4096; f += 256) {
            int c = f >> 4, j4 = f & 15;
            CP_ASYNC16(vdst + (c * VSTRW + j4 * 4) * 4, vgb + (size_t)c * NN + j4 * 8);
        }
        CP_COMMIT();
    }

    uint32_t* ps = sm + OPS;

    for (int jt = 0; jt < NN / TJ; jt++) {
        const int cur = jt & 1;
        __syncthreads();   // old buffer + P fully consumed

        if (jt + 1 < NN / TJ) {
            const int j0n = (jt + 1) * TJ;
            const __nv_bfloat16* kg = kgb + (size_t)j0n * DA;
            uint32_t kdst = smb + (cur ? OKS0 : OKS1) * 4;
#pragma unroll
            for (int f = t; f < 1024; f += 256) {
                int r = f >> 3, c4 = f & 7;
                CP_ASYNC16(kdst + (r * KSTRW + c4 * 4) * 4, kg + (size_t)r * DA + c4 * 8);
            }
            const __nv_bfloat16* vg = vgb + j0n;
            uint32_t vdst = smb + (cur ? OVS0 : OVS1) * 4;
#pragma unroll
            for (int f = t; f < 4096; f += 256) {
                int c = f >> 4, j4 = f & 15;
                CP_ASYNC16(vdst + (c * VSTRW + j4 * 4) * 4, vg + (size_t)c * NN + j4 * 8);
            }
            CP_COMMIT();
            CP_WAIT(1);
        } else {
            CP_WAIT(0);
        }
        __syncthreads();

        const uint32_t kbase = smb + (cur ? OKS1 : OKS0) * 4 + krowpart;
        const uint32_t vbase = smb + (cur ? OVS1 : OVS0) * 4 + vrowpart;

        // ==== S: 16 rows x own 64-j half (4 jb-blocks), no redundancy ====
        float sf[8][4];
#pragma unroll
        for (int n = 0; n < 8; n++)
#pragma unroll
            for (int r = 0; r < 4; r++) sf[n][r] = 0.f;
#pragma unroll
        for (int s = 0; s < 4; s++) {
#pragma unroll
            for (int jb = 0; jb < 4; jb++) {
                uint32_t b0, b1, b2, b3;
                LDSM_X4(b0, b1, b2, b3, kbase + 4 * ((jh * 64 + jb * 16) * KSTRW + s * 8));
                MMA_BF16(sf[jb*2][0], sf[jb*2][1], sf[jb*2][2], sf[jb*2][3],
                         qa[s][0], qa[s][1], qa[s][2], qa[s][3], b0, b1);
                MMA_BF16(sf[jb*2+1][0], sf[jb*2+1][1], sf[jb*2+1][2], sf[jb*2+1][3],
                         qa[s][0], qa[s][1], qa[s][2], qa[s][3], b2, b3);
            }
        }

        // ---- exp + pack + store P (rows ig*16+{g,g+8}, cols jh*64+nb*8+2tg) ----
#pragma unroll
        for (int nb = 0; nb < 8; nb++) {
            float e0, e1, e2, e3;
            asm("ex2.approx.ftz.f32 %0, %1;" : "=f"(e0) : "f"(sf[nb][0]));
            asm("ex2.approx.ftz.f32 %0, %1;" : "=f"(e1) : "f"(sf[nb][1]));
            asm("ex2.approx.ftz.f32 %0, %1;" : "=f"(e2) : "f"(sf[nb][2]));
            asm("ex2.approx.ftz.f32 %0, %1;" : "=f"(e3) : "f"(sf[nb][3]));
            l0 += e0 + e1;
            l1 += e2 + e3;
            uint32_t w0, w1;
            PACK_BF16X2(w0, e0, e1);
            PACK_BF16X2(w1, e2, e3);
            int colw = jh * 32 + nb * 4 + tg;
            ps[(ig * 16 + g    ) * PSTRW + colw] = w0;
            ps[(ig * 16 + g + 8) * PSTRW + colw] = w1;
        }
        __syncthreads();   // P tile complete

        // ==== PV: 16 rows x own 128-c half, full j (8 k16-steps) ====
#pragma unroll
        for (int s = 0; s < 8; s++) {
            uint32_t a0[4];
            LDSM_X4(a0[0], a0[1], a0[2], a0[3], pldbase + 4 * (s * 8));
#pragma unroll
            for (int nbp = 0; nbp < 8; nbp++) {
                uint32_t b0, b1, b2, b3;
                LDSM_X4(b0, b1, b2, b3, vbase + 4 * (nbp * 16 * VSTRW + s * 8));
                MMA_BF16(o[nbp*2][0], o[nbp*2][1], o[nbp*2][2], o[nbp*2][3],
                         a0[0], a0[1], a0[2], a0[3], b0, b1);
                MMA_BF16(o[nbp*2+1][0], o[nbp*2+1][1], o[nbp*2+1][2], o[nbp*2+1][3],
                         a0[0], a0[1], a0[2], a0[3], b2, b3);
            }
        }
    }

    // ---- l: quad reduce, then combine the two jh halves via smem ----
    float* lsum = (float*)(sm + OLS);
    l0 += __shfl_xor_sync(0xffffffffu, l0, 1);
    l0 += __shfl_xor_sync(0xffffffffu, l0, 2);
    l1 += __shfl_xor_sync(0xffffffffu, l1, 1);
    l1 += __shfl_xor_sync(0xffffffffu, l1, 2);
    __syncthreads();
    if (tg == 0) {
        lsum[jh * 64 + ig * 16 + g    ] = l0;
        lsum[jh * 64 + ig * 16 + g + 8] = l1;
    }
    __syncthreads();
    const int rlo = ig * 16 + g;
    const float linv0 = 1.0f / (lsum[rlo    ] + lsum[64 + rlo    ]);
    const float linv1 = 1.0f / (lsum[rlo + 8] + lsum[64 + rlo + 8]);

    // ---- epilogue: out[b][c][i] = O/l + x ----
    const int r0 = i0 + rlo;
#pragma unroll
    for (int nb = 0; nb < 16; nb++) {
        int c = ch * 128 + nb * 8 + 2 * tg;
        size_t b0i = ((size_t)b * CC + c) * NN;
        size_t b1i = ((size_t)b * CC + c + 1) * NN;
        out[b0i + r0]     = fmaf(o[nb][0], linv0, x[b0i + r0]);
        out[b1i + r0]     = fmaf(o[nb][1], linv0, x[b1i + r0]);
        out[b0i + r0 + 8] = fmaf(o[nb][2], linv1, x[b0i + r0 + 8]);
        out[b1i + r0 + 8] = fmaf(o[nb][3], linv1, x[b1i + r0 + 8]);
    }
}

// ---------------------------------------------------------------------------
extern "C" void kernel_launch(void* const* d_in, const int* in_sizes, int n_in,
                              void* d_out, int out_size)
{
    const float* x  = (const float*)d_in[0];
    const float* Wq = (const float*)d_in[1];
    const float* bq = (const float*)d_in[2];
    const float* Wk = (const float*)d_in[3];
    const float* bk = (const float*)d_in[4];
    const float* Wv = (const float*)d_in[5];
    const float* bv = (const float*)d_in[6];
    float* out = (float*)d_out;

    cudaFuncSetAttribute(proj_kernel, cudaFuncAttributeMaxDynamicSharedMemorySize, PSMW * 4);
    cudaFuncSetAttribute(attn_kernel, cudaFuncAttributeMaxDynamicSharedMemorySize, SMW * 4);

    proj_kernel<<<dim3(8, 3, BB), 256, PSMW * 4>>>(x, Wq, bq, Wk, bk, Wv, bv);
    attn_kernel<<<dim3(NN / TI, BB), 256, SMW * 4>>>(x, out);
}

// round 17
// speedup vs baseline: 1.1023x; 1.1023x over previous
#include <cuda_runtime.h>
#include <cuda_bf16.h>
#include <cstdint>

#define BB 16
#define CC 256
#define NN 4096
#define DA 64
#define TI 128
#define TJ 128

typedef unsigned long long u64;

#define MMA_BF16(d0,d1,d2,d3,a0,a1,a2,a3,b0,b1) \
    asm volatile("mma.sync.aligned.m16n8k16.row.col.f32.bf16.bf16.f32 " \
        "{%0,%1,%2,%3}, {%4,%5,%6,%7}, {%8,%9}, {%0,%1,%2,%3};" \
        : "+f"(d0), "+f"(d1), "+f"(d2), "+f"(d3) \
        : "r"(a0), "r"(a1), "r"(a2), "r"(a3), "r"(b0), "r"(b1))

// fp8 e4m3 m16n8k32 (sm_89+): same operand shape, k=32 per instruction
#define MMA_FP8(d0,d1,d2,d3,a0,a1,a2,a3,b0,b1) \
    asm volatile("mma.sync.aligned.m16n8k32.row.col.f32.e4m3.e4m3.f32 " \
        "{%0,%1,%2,%3}, {%4,%5,%6,%7}, {%8,%9}, {%0,%1,%2,%3};" \
        : "+f"(d0), "+f"(d1), "+f"(d2), "+f"(d3) \
        : "r"(a0), "r"(a1), "r"(a2), "r"(a3), "r"(b0), "r"(b1))

#define PACK_BF16X2(d, lo, hi) \
    asm("cvt.rn.bf16x2.f32 %0, %1, %2;" : "=r"(d) : "f"(hi), "f"(lo))

// pack two f32 -> e4m3x2 (16 bits; low byte = lo)
#define PACK_E4M3X2(d, lo, hi) \
    asm("cvt.rn.satfinite.e4m3x2.f32 %0, %1, %2;" : "=h"(d) : "f"(hi), "f"(lo))

#define LDSM_X4(r0,r1,r2,r3, addr) \
    asm volatile("ldmatrix.sync.aligned.m8n8.x4.shared.b16 {%0,%1,%2,%3}, [%4];" \
        : "=r"(r0), "=r"(r1), "=r"(r2), "=r"(r3) : "r"(addr))

#define LDSM_T_X4(r0,r1,r2,r3, addr) \
    asm volatile("ldmatrix.sync.aligned.m8n8.x4.trans.shared.b16 {%0,%1,%2,%3}, [%4];" \
        : "=r"(r0), "=r"(r1), "=r"(r2), "=r"(r3) : "r"(addr))

// cp.async (sm_80+)
#define CP_ASYNC16(dst, src) \
    asm volatile("cp.async.cg.shared.global [%0], [%1], 16;" :: "r"(dst), "l"(src) : "memory")
#define CP_COMMIT() asm volatile("cp.async.commit_group;" ::: "memory")
#define CP_WAIT(n)  asm volatile("cp.async.wait_group %0;" :: "n"(n) : "memory")

// Scratch: q/k in raw e4m3 (UNscaled), v in bf16 transposed
__device__ uint8_t       g_q[(size_t)BB * NN * DA];   // [b][n][a] e4m3
__device__ uint8_t       g_k[(size_t)BB * NN * DA];   // [b][n][a] e4m3
__device__ __nv_bfloat16 g_v[(size_t)BB * CC * NN];   // [b][c][n] bf16

__device__ __forceinline__ uint32_t smem_u32(const void* p) {
    uint32_t a;
    asm("{ .reg .u64 t; cvta.to.shared.u64 t, %1; cvt.u32.u64 %0, t; }" : "=r"(a) : "l"(p));
    return a;
}

// ---------------------------------------------------------------------------
// Kernel 1: fused QKV projection via bf16 mma.sync; q/k emitted as e4m3.
// ---------------------------------------------------------------------------
#define PW_STR 132
#define PX_STR 68
#define POW  0
#define POX0 (128 * PW_STR)
#define POX1 (POX0 + 64 * PX_STR)
#define PSMW (POX1 + 64 * PX_STR)

__global__ __launch_bounds__(256, 1) void proj_kernel(
    const float* __restrict__ x,
    const float* __restrict__ Wq, const float* __restrict__ bq,
    const float* __restrict__ Wk, const float* __restrict__ bk,
    const float* __restrict__ Wv, const float* __restrict__ bv)
{
    extern __shared__ __align__(16) uint32_t psm[];
    const uint32_t smb = smem_u32(psm);

    const int t    = threadIdx.x;
    const int lane = t & 31;
    const int wid  = t >> 5;
    const int g    = lane >> 2;
    const int tg   = lane & 3;
    const int lrow = lane & 7;
    const int q8   = lane >> 3;
    const int rg   = blockIdx.y;
    const int b    = blockIdx.z;
    const int nbase = blockIdx.x * 512;

    for (int f = t; f < 128 * 128; f += 256) {
        int r = f >> 7, cw = f & 127;
        const float* wrow;
        if (rg == 0) wrow = (r < 64) ? (Wq + r * CC) : (Wk + (r - 64) * CC);
        else         wrow = Wv + ((size_t)((rg - 1) * 128 + r)) * CC;
        float2 wv = *(const float2*)&wrow[cw * 2];
        uint32_t pk; PACK_BF16X2(pk, wv.x, wv.y);
        psm[r * PW_STR + cw] = pk;
    }
    __syncthreads();

    uint32_t af[16][4];
    {
        const uint32_t abase = smb + 4 * ((wid * 16 + (q8 & 1) * 8 + lrow) * PW_STR + (q8 >> 1) * 4);
#pragma unroll
        for (int s = 0; s < 16; s++)
            LDSM_X4(af[s][0], af[s][1], af[s][2], af[s][3], abase + 4 * (s * 8));
    }

    const int row_g = wid * 16 + g;
    float bias_lo, bias_hi;
    if (rg == 0) {
        if (wid < 4) { bias_lo = bq[row_g]; bias_hi = bq[row_g + 8]; }
        else         { bias_lo = bk[row_g - 64]; bias_hi = bk[row_g - 56]; }
    } else {
        bias_lo = bv[(rg - 1) * 128 + row_g];
        bias_hi = bv[(rg - 1) * 128 + row_g + 8];
    }

    const uint32_t xrowpart = ((q8 & 1) * 8 + lrow) * PX_STR * 4 + (q8 >> 1) * 16;

    float4 pf[8];
#pragma unroll
    for (int i = 0; i < 8; i++)
        pf[i] = *(const float4*)&x[((size_t)b * CC + i * 8 + (t >> 5)) * NN + nbase + (t & 31) * 4];

    for (int tile = 0; tile < 4; tile++) {
        const int n0 = nbase + tile * 128;

        float acc[16][4];
#pragma unroll
        for (int nb = 0; nb < 16; nb++)
#pragma unroll
            for (int r = 0; r < 4; r++) acc[nb][r] = 0.f;

        for (int ck = 0; ck < 4; ck++) {
            __syncthreads();
            uint32_t* xb = psm + ((ck & 1) ? POX1 : POX0);
#pragma unroll
            for (int i = 0; i < 8; i++) {
                int c = i * 8 + (t >> 5);
                uint32_t w0, w1;
                PACK_BF16X2(w0, pf[i].x, pf[i].y);
                PACK_BF16X2(w1, pf[i].z, pf[i].w);
                *(uint2*)&xb[c * PX_STR + (t & 31) * 2] = make_uint2(w0, w1);
            }
            __syncthreads();

            if (ck < 3) {
                int cb = (ck + 1) * 64;
#pragma unroll
                for (int i = 0; i < 8; i++)
                    pf[i] = *(const float4*)&x[((size_t)b * CC + cb + i * 8 + (t >> 5)) * NN + n0 + (t & 31) * 4];
            } else if (tile < 3) {
                int n0n = nbase + (tile + 1) * 128;
#pragma unroll
                for (int i = 0; i < 8; i++)
                    pf[i] = *(const float4*)&x[((size_t)b * CC + i * 8 + (t >> 5)) * NN + n0n + (t & 31) * 4];
            }

            const uint32_t xtbase = smb + 4 * ((ck & 1) ? POX1 : POX0) + xrowpart;
#pragma unroll
            for (int s = 0; s < 4; s++) {
                const int astep = ck * 4 + s;
#pragma unroll
                for (int nbp = 0; nbp < 8; nbp++) {
                    uint32_t b0, b1, b2, b3;
                    LDSM_T_X4(b0, b1, b2, b3, xtbase + s * 16 * PX_STR * 4 + nbp * 32);
                    MMA_BF16(acc[nbp*2][0], acc[nbp*2][1], acc[nbp*2][2], acc[nbp*2][3],
                             af[astep][0], af[astep][1], af[astep][2], af[astep][3], b0, b1);
                    MMA_BF16(acc[nbp*2+1][0], acc[nbp*2+1][1], acc[nbp*2+1][2], acc[nbp*2+1][3],
                             af[astep][0], af[astep][1], af[astep][2], af[astep][3], b2, b3);
                }
            }
        }

        if (rg != 0) {
            const int clo = (rg - 1) * 128 + wid * 16 + g;
#pragma unroll
            for (int nb = 0; nb < 16; nb++) {
                uint32_t w0, w1;
                PACK_BF16X2(w0, acc[nb][0] + bias_lo, acc[nb][1] + bias_lo);
                PACK_BF16X2(w1, acc[nb][2] + bias_hi, acc[nb][3] + bias_hi);
                *(uint32_t*)&g_v[((size_t)b * CC + clo) * NN + n0 + nb * 8 + 2 * tg] = w0;
                *(uint32_t*)&g_v[((size_t)b * CC + clo + 8) * NN + n0 + nb * 8 + 2 * tg] = w1;
            }
        } else {
            // q/k: bounce through smem (bf16), then convert to e4m3 on the
            // transposed gather. NOTE: q stored RAW (no scale) for fp8 range.
            __syncthreads();
            uint32_t* dstbuf = psm + ((wid < 4) ? POX0 : POX1);
            const int rloc = (wid & 3) * 16 + g;
#pragma unroll
            for (int nb = 0; nb < 16; nb++) {
                uint32_t w0, w1;
                PACK_BF16X2(w0, acc[nb][0] + bias_lo, acc[nb][1] + bias_lo);
                PACK_BF16X2(w1, acc[nb][2] + bias_hi, acc[nb][3] + bias_hi);
                dstbuf[(rloc    ) * PX_STR + nb * 4 + tg] = w0;
                dstbuf[(rloc + 8) * PX_STR + nb * 4 + tg] = w1;
            }
            __syncthreads();
            const int nn = t & 127, half = t >> 7;
            const uint16_t* s16q = (const uint16_t*)(psm + POX0);
            const uint16_t* s16k = (const uint16_t*)(psm + POX1);
            uint32_t w8[8];
#pragma unroll
            for (int i = 0; i < 16; i++) {
                uint32_t lo = s16q[(half * 32 + 2 * i    ) * (PX_STR * 2) + nn];
                uint32_t hi = s16q[(half * 32 + 2 * i + 1) * (PX_STR * 2) + nn];
                float f0 = __uint_as_float(lo << 16);
                float f1 = __uint_as_float(hi << 16);
                uint16_t p; PACK_E4M3X2(p, f0, f1);
                if ((i & 1) == 0) w8[i >> 1] = (uint32_t)p;
                else              w8[i >> 1] |= ((uint32_t)p) << 16;
            }
            {
                uint4* p = (uint4*)&g_q[((size_t)(b) * NN + n0 + nn) * DA + half * 32];
                p[0] = make_uint4(w8[0], w8[1], w8[2], w8[3]);
                p[1] = make_uint4(w8[4], w8[5], w8[6], w8[7]);
            }
#pragma unroll
            for (int i = 0; i < 16; i++) {
                uint32_t lo = s16k[(half * 32 + 2 * i    ) * (PX_STR * 2) + nn];
                uint32_t hi = s16k[(half * 32 + 2 * i + 1) * (PX_STR * 2) + nn];
                float f0 = __uint_as_float(lo << 16);
                float f1 = __uint_as_float(hi << 16);
                uint16_t p; PACK_E4M3X2(p, f0, f1);
                if ((i & 1) == 0) w8[i >> 1] = (uint32_t)p;
                else              w8[i >> 1] |= ((uint32_t)p) << 16;
            }
            {
                uint4* p = (uint4*)&g_k[((size_t)(b) * NN + n0 + nn) * DA + half * 32];
                p[0] = make_uint4(w8[0], w8[1], w8[2], w8[3]);
                p[1] = make_uint4(w8[4], w8[5], w8[6], w8[7]);
            }
        }
    }
}

// ---------------------------------------------------------------------------
// Kernel 2: flash attention. S-GEMM in fp8 e4m3 (m16n8k32, half the MMAs),
// PV in bf16. TI=TJ=128, 8 warps x 16 rows, P-in-registers (R13 baseline).
// ---------------------------------------------------------------------------
#define KSTRW 20                  // K row stride (words): 16 data (64 e4m3) + 4 pad
#define VSTRW 68                  // V row stride (words)
#define KW  (TJ * KSTRW)          // 2560
#define VW  (CC * VSTRW)          // 17408
#define OKS0 0
#define OVS0 KW
#define OKS1 (KW + VW)
#define OVS1 (2 * KW + VW)
#define SMW  (2 * (KW + VW))      // 39936 words = 159744 B

__global__ __launch_bounds__(256, 1) void attn_kernel(
    const float* __restrict__ x, float* __restrict__ out)
{
    extern __shared__ __align__(16) uint32_t sm[];
    const uint32_t smb = smem_u32(sm);

    const int t    = threadIdx.x;
    const int lane = t & 31;
    const int wid  = t >> 5;       // 8 warps x 16 i-rows
    const int g    = lane >> 2;
    const int tg   = lane & 3;
    const int b    = blockIdx.y;
    const int i0   = blockIdx.x * TI;

    const int lrow = lane & 7;
    const int q8   = lane >> 3;
    const int bqr  = q8 >> 1, bqc = q8 & 1;
    const uint32_t krowpart = 4 * ((bqr * 8 + lrow) * KSTRW + bqc * 4);
    const uint32_t vrowpart = 4 * ((bqr * 8 + lrow) * VSTRW + bqc * 4);

    const float SCALE = 1.4426950408889634f / 64.0f;   // log2(e)/sqrt(N)

    // ---- Q fragments (e4m3, 2 k32-steps), loaded once from global ----
    uint32_t qa[2][4];
    {
        const uint8_t* qg = g_q + ((size_t)b * NN + i0 + wid * 16) * DA;
#pragma unroll
        for (int s = 0; s < 2; s++) {
            qa[s][0] = *(const uint32_t*)&qg[(size_t)(g    ) * DA + s * 32 + 4 * tg     ];
            qa[s][1] = *(const uint32_t*)&qg[(size_t)(g + 8) * DA + s * 32 + 4 * tg     ];
            qa[s][2] = *(const uint32_t*)&qg[(size_t)(g    ) * DA + s * 32 + 16 + 4 * tg];
            qa[s][3] = *(const uint32_t*)&qg[(size_t)(g + 8) * DA + s * 32 + 16 + 4 * tg];
        }
    }

    float o[32][4];
#pragma unroll
    for (int n = 0; n < 32; n++)
#pragma unroll
        for (int r = 0; r < 4; r++) o[n][r] = 0.f;

    float l0 = 0.f, l1 = 0.f;

    const uint8_t* kgb = g_k + (size_t)b * NN * DA;
    const __nv_bfloat16* vgb = g_v + (size_t)b * CC * NN;

    // ---- prologue: stage tile 0 into buffer 0 ----
    {
        uint32_t kdst = smb + OKS0 * 4;
#pragma unroll
        for (int f = t; f < 512; f += 256) {
            int r = f >> 2, c4 = f & 3;
            CP_ASYNC16(kdst + (r * KSTRW + c4 * 4) * 4, kgb + (size_t)r * DA + c4 * 16);
        }
        uint32_t vdst = smb + OVS0 * 4;
#pragma unroll
        for (int f = t; f < 4096; f += 256) {
            int c = f >> 4, j4 = f & 15;
            CP_ASYNC16(vdst + (c * VSTRW + j4 * 4) * 4, vgb + (size_t)c * NN + j4 * 8);
        }
        CP_COMMIT();
    }

    for (int jt = 0; jt < NN / TJ; jt++) {
        const int cur = jt & 1;
        __syncthreads();

        if (jt + 1 < NN / TJ) {
            const int j0n = (jt + 1) * TJ;
            const uint8_t* kg = kgb + (size_t)j0n * DA;
            uint32_t kdst = smb + (cur ? OKS0 : OKS1) * 4;
#pragma unroll
            for (int f = t; f < 512; f += 256) {
                int r = f >> 2, c4 = f & 3;
                CP_ASYNC16(kdst + (r * KSTRW + c4 * 4) * 4, kg + (size_t)r * DA + c4 * 16);
            }
            const __nv_bfloat16* vg = vgb + j0n;
            uint32_t vdst = smb + (cur ? OVS0 : OVS1) * 4;
#pragma unroll
            for (int f = t; f < 4096; f += 256) {
                int c = f >> 4, j4 = f & 15;
                CP_ASYNC16(vdst + (c * VSTRW + j4 * 4) * 4, vg + (size_t)c * NN + j4 * 8);
            }
            CP_COMMIT();
            CP_WAIT(1);
        } else {
            CP_WAIT(0);
        }
        __syncthreads();

        const uint32_t kbase = smb + (cur ? OKS1 : OKS0) * 4 + krowpart;
        const uint32_t vbase = smb + (cur ? OVS1 : OVS0) * 4 + vrowpart;

        // ======== j-half 0: S (fp8, 2 k32-steps) ========
        float sf[8][4];
#pragma unroll
        for (int n = 0; n < 8; n++)
#pragma unroll
            for (int r = 0; r < 4; r++) sf[n][r] = 0.f;
#pragma unroll
        for (int s = 0; s < 2; s++) {
#pragma unroll
            for (int nbp = 0; nbp < 4; nbp++) {
                uint32_t b0, b1, b2, b3;
                LDSM_X4(b0, b1, b2, b3, kbase + 4 * (nbp * 16 * KSTRW + s * 8));
                MMA_FP8(sf[nbp*2][0], sf[nbp*2][1], sf[nbp*2][2], sf[nbp*2][3],
                        qa[s][0], qa[s][1], qa[s][2], qa[s][3], b0, b1);
                MMA_FP8(sf[nbp*2+1][0], sf[nbp*2+1][1], sf[nbp*2+1][2], sf[nbp*2+1][3],
                        qa[s][0], qa[s][1], qa[s][2], qa[s][3], b2, b3);
            }
        }

        // ---- exp(h0) (apply scale here) -> pa0 ----
        uint32_t pa0[4][4];
#pragma unroll
        for (int nb = 0; nb < 8; nb++) {
            float e0, e1, e2, e3;
            asm("ex2.approx.ftz.f32 %0, %1;" : "=f"(e0) : "f"(sf[nb][0] * SCALE));
            asm("ex2.approx.ftz.f32 %0, %1;" : "=f"(e1) : "f"(sf[nb][1] * SCALE));
            asm("ex2.approx.ftz.f32 %0, %1;" : "=f"(e2) : "f"(sf[nb][2] * SCALE));
            asm("ex2.approx.ftz.f32 %0, %1;" : "=f"(e3) : "f"(sf[nb][3] * SCALE));
            l0 += e0 + e1;
            l1 += e2 + e3;
            int s = nb >> 1, hi = (nb & 1) * 2;
            PACK_BF16X2(pa0[s][hi    ], e0, e1);
            PACK_BF16X2(pa0[s][hi + 1], e2, e3);
        }

        // ======== j-half 1: S (rows 64..127 of K tile) ========
#pragma unroll
        for (int n = 0; n < 8; n++)
#pragma unroll
            for (int r = 0; r < 4; r++) sf[n][r] = 0.f;
#pragma unroll
        for (int s = 0; s < 2; s++) {
#pragma unroll
            for (int nbp = 0; nbp < 4; nbp++) {
                uint32_t b0, b1, b2, b3;
                LDSM_X4(b0, b1, b2, b3, kbase + 4 * ((64 + nbp * 16) * KSTRW + s * 8));
                MMA_FP8(sf[nbp*2][0], sf[nbp*2][1], sf[nbp*2][2], sf[nbp*2][3],
                        qa[s][0], qa[s][1], qa[s][2], qa[s][3], b0, b1);
                MMA_FP8(sf[nbp*2+1][0], sf[nbp*2+1][1], sf[nbp*2+1][2], sf[nbp*2+1][3],
                        qa[s][0], qa[s][1], qa[s][2], qa[s][3], b2, b3);
            }
        }

        // ======== PV(h0): bf16, k-steps 0..3 with pa0 ========
#pragma unroll
        for (int s = 0; s < 4; s++) {
#pragma unroll
            for (int nbp = 0; nbp < 16; nbp++) {
                uint32_t b0, b1, b2, b3;
                LDSM_X4(b0, b1, b2, b3, vbase + 4 * (nbp * 16 * VSTRW + s * 8));
                MMA_BF16(o[nbp*2][0], o[nbp*2][1], o[nbp*2][2], o[nbp*2][3],
                         pa0[s][0], pa0[s][1], pa0[s][2], pa0[s][3], b0, b1);
                MMA_BF16(o[nbp*2+1][0], o[nbp*2+1][1], o[nbp*2+1][2], o[nbp*2+1][3],
                         pa0[s][0], pa0[s][1], pa0[s][2], pa0[s][3], b2, b3);
            }
        }

        // ---- exp(h1) -> pa1 ----
        uint32_t pa1[4][4];
#pragma unroll
        for (int nb = 0; nb < 8; nb++) {
            float e0, e1, e2, e3;
            asm("ex2.approx.ftz.f32 %0, %1;" : "=f"(e0) : "f"(sf[nb][0] * SCALE));
            asm("ex2.approx.ftz.f32 %0, %1;" : "=f"(e1) : "f"(sf[nb][1] * SCALE));
            asm("ex2.approx.ftz.f32 %0, %1;" : "=f"(e2) : "f"(sf[nb][2] * SCALE));
            asm("ex2.approx.ftz.f32 %0, %1;" : "=f"(e3) : "f"(sf[nb][3] * SCALE));
            l0 += e0 + e1;
            l1 += e2 + e3;
            int s = nb >> 1, hi = (nb & 1) * 2;
            PACK_BF16X2(pa1[s][hi    ], e0, e1);
            PACK_BF16X2(pa1[s][hi + 1], e2, e3);
        }

        // ======== PV(h1): k-steps 4..7 with pa1 ========
#pragma unroll
        for (int s = 0; s < 4; s++) {
#pragma unroll
            for (int nbp = 0; nbp < 16; nbp++) {
                uint32_t b0, b1, b2, b3;
                LDSM_X4(b0, b1, b2, b3, vbase + 4 * (nbp * 16 * VSTRW + (s + 4) * 8));
                MMA_BF16(o[nbp*2][0], o[nbp*2][1], o[nbp*2][2], o[nbp*2][3],
                         pa1[s][0], pa1[s][1], pa1[s][2], pa1[s][3], b0, b1);
                MMA_BF16(o[nbp*2+1][0], o[nbp*2+1][1], o[nbp*2+1][2], o[nbp*2+1][3],
                         pa1[s][0], pa1[s][1], pa1[s][2], pa1[s][3], b2, b3);
            }
        }
    }

    // ---- l complete within warp: quad reduce ----
    l0 += __shfl_xor_sync(0xffffffffu, l0, 1);
    l0 += __shfl_xor_sync(0xffffffffu, l0, 2);
    l1 += __shfl_xor_sync(0xffffffffu, l1, 1);
    l1 += __shfl_xor_sync(0xffffffffu, l1, 2);
    const float linv0 = 1.0f / l0;
    const float linv1 = 1.0f / l1;

    // ---- epilogue: out[b][c][i] = O/l + x ----
    const int r0 = i0 + wid * 16 + g;
#pragma unroll
    for (int nb = 0; nb < 32; nb++) {
        int c = nb * 8 + 2 * tg;
        size_t b0i = ((size_t)b * CC + c) * NN;
        size_t b1i = ((size_t)b * CC + c + 1) * NN;
        out[b0i + r0]     = fmaf(o[nb][0], linv0, x[b0i + r0]);
        out[b1i + r0]     = fmaf(o[nb][1], linv0, x[b1i + r0]);
        out[b0i + r0 + 8] = fmaf(o[nb][2], linv1, x[b0i + r0 + 8]);
        out[b1i + r0 + 8] = fmaf(o[nb][3], linv1, x[b1i + r0 + 8]);
    }
}

// ---------------------------------------------------------------------------
extern "C" void kernel_launch(void* const* d_in, const int* in_sizes, int n_in,
                              void* d_out, int out_size)
{
    const float* x  = (const float*)d_in[0];
    const float* Wq = (const float*)d_in[1];
    const float* bq = (const float*)d_in[2];
    const float* Wk = (const float*)d_in[3];
    const float* bk = (const float*)d_in[4];
    const float* Wv = (const float*)d_in[5];
    const float* bv = (const float*)d_in[6];
    float* out = (float*)d_out;

    cudaFuncSetAttribute(proj_kernel, cudaFuncAttributeMaxDynamicSharedMemorySize, PSMW * 4);
    cudaFuncSetAttribute(attn_kernel, cudaFuncAttributeMaxDynamicSharedMemorySize, SMW * 4);

    proj_kernel<<<dim3(8, 3, BB), 256, PSMW * 4>>>(x, Wq, bq, Wk, bk, Wv, bv);
    attn_kernel<<<dim3(NN / TI, BB), 256, SMW * 4>>>(x, out);
}